// round 12
// baseline (speedup 1.0000x reference)
#include <cuda_runtime.h>
#include <cstdint>

#define BATCH 32
#define SEQ   512
#define HID   256
#define TMEL  2000
#define H4    (HID / 4)      // 64 float4 per row (1KB rows)
#define CHUNK 8              // input rows per CTA
#define NCHUNK (SEQ / CHUNK) // 64 CTAs per batch

__global__ __launch_bounds__(256, 8)
void length_regulator_kernel(const float* __restrict__ x,
                             const int* __restrict__ duration,
                             float* __restrict__ out,
                             int out_size) {
    const int b     = blockIdx.y;
    const int chunk = blockIdx.x;        // 0..63
    const int tid   = threadIdx.x;
    const int wid   = tid >> 5;
    const int lane5 = tid & 31;
    const int lane  = tid & 63;          // float4 slot within a row
    const int grp   = tid >> 6;          // 0..3 (row group, 2 rows each)

    __shared__ int csum[SEQ];
    __shared__ int wsum[8];
    // Per-group staging rows for bulk stores: [grp][0]=row r0, [1]=row r0+1,
    // [2]=last row (tail replication). 12 KB.
    __shared__ __align__(128) float4 rowbuf[4][3][H4];

    // ---- dur load FIRST (heads the dependent scan chain). ----
    const int2* dur2 = (const int2*)(duration + b * SEQ);
    int2 d = dur2[tid];

    // ---- Independent x loads fill the dur-load shadow. ----
    const float4* __restrict__ xb = (const float4*)x + (b * SEQ) * H4;
    const int r0 = chunk * CHUNK + grp * 2;       // rows r0, r0+1
    float4 v0    = __ldg(&xb[(r0 + 0) * H4 + lane]);
    float4 v1    = __ldg(&xb[(r0 + 1) * H4 + lane]);
    float4 vlast = __ldg(&xb[(SEQ - 1) * H4 + lane]);

    // ---- Inclusive scan of 512 durations (shuffle-based). ----
    int sc = d.x + d.y;
    #pragma unroll
    for (int off = 1; off < 32; off <<= 1) {
        int t = __shfl_up_sync(0xffffffffu, sc, off);
        if (lane5 >= off) sc += t;
    }
    if (lane5 == 31) wsum[wid] = sc;

    // Stage the three rows while the scan's smem round-trip settles.
    rowbuf[grp][0][lane] = v0;
    rowbuf[grp][1][lane] = v1;
    rowbuf[grp][2][lane] = vlast;

    __syncthreads();
    int wprefix = 0;
    #pragma unroll
    for (int w = 0; w < 8; w++)
        wprefix += (w < wid) ? wsum[w] : 0;
    int inc_hi = sc + wprefix;                    // cumsum at elem 2*tid+1
    csum[2 * tid]     = inc_hi - d.y;
    csum[2 * tid + 1] = inc_hi;
    __syncthreads();   // orders csum AND rowbuf for all threads

    // ---- Bulk-store expansion: row i covers output rows [csum[i-1], csum[i]),
    //      which are CONTIGUOUS 1KB blocks. One elected thread per group
    //      issues one cp.async.bulk (1KB, smem->gmem) per output row;
    //      stores leave the per-warp LSU path entirely. ----
    float4* __restrict__ ob = (float4*)out + (b * TMEL) * H4;
    int tc = min(csum[SEQ - 1], TMEL);

    if (lane == 0) {
        // Make generic-proxy smem writes visible to the async proxy.
        asm volatile("fence.proxy.async.shared::cta;" ::: "memory");

        uint32_t s0 = (uint32_t)__cvta_generic_to_shared(&rowbuf[grp][0][0]);
        uint32_t s1 = (uint32_t)__cvta_generic_to_shared(&rowbuf[grp][1][0]);
        uint32_t s2 = (uint32_t)__cvta_generic_to_shared(&rowbuf[grp][2][0]);

        int lo0 = (r0 == 0) ? 0 : csum[r0 - 1];
        int hi0 = min(csum[r0], TMEL);
        int hi1 = min(csum[r0 + 1], TMEL);

        for (int t = lo0; t < hi0; t++)
            asm volatile("cp.async.bulk.global.shared::cta.bulk_group [%0], [%1], %2;"
                         :: "l"(ob + t * H4), "r"(s0), "n"(HID * 4) : "memory");
        for (int t = hi0; t < hi1; t++)
            asm volatile("cp.async.bulk.global.shared::cta.bulk_group [%0], [%1], %2;"
                         :: "l"(ob + t * H4), "r"(s1), "n"(HID * 4) : "memory");

        // Tail: [tc, TMEL) replicates row SEQ-1; spread across the 256
        // (chunk,grp) slots of this batch, stride 256.
        for (int t = tc + chunk * 4 + grp; t < TMEL; t += 4 * NCHUNK)
            asm volatile("cp.async.bulk.global.shared::cta.bulk_group [%0], [%1], %2;"
                         :: "l"(ob + t * H4), "r"(s2), "n"(HID * 4) : "memory");

        asm volatile("cp.async.bulk.commit_group;" ::: "memory");
        asm volatile("cp.async.bulk.wait_group 0;" ::: "memory");
    }

    // ---- mel_len appended after main output (if buffer includes it). ----
    if (chunk == 0 && tid == 0) {
        const int main_elems = BATCH * TMEL * HID;
        if (out_size >= main_elems + BATCH)
            out[main_elems + b] = (float)tc;
    }
}

extern "C" void kernel_launch(void* const* d_in, const int* in_sizes, int n_in,
                              void* d_out, int out_size) {
    const float* x        = (const float*)d_in[0];
    const int*   duration = (const int*)d_in[1];
    float*       out      = (float*)d_out;

    dim3 grid(NCHUNK, BATCH);   // (64, 32) = 2048 CTAs
    length_regulator_kernel<<<grid, 256>>>(x, duration, out, out_size);
}

// round 13
// speedup vs baseline: 1.0934x; 1.0934x over previous
#include <cuda_runtime.h>

#define BATCH 32
#define SEQ   512
#define HID   256
#define TMEL  2000
#define H4    (HID / 4)      // 64 float4 per row
#define CHUNK 8              // input rows per CTA
#define NCHUNK (SEQ / CHUNK) // 64 CTAs per batch

__global__ __launch_bounds__(256, 8)
void length_regulator_kernel(const float* __restrict__ x,
                             const int* __restrict__ duration,
                             float* __restrict__ out,
                             int out_size) {
    const int b     = blockIdx.y;
    const int chunk = blockIdx.x;        // 0..63
    const int tid   = threadIdx.x;
    const int wid   = tid >> 5;
    const int lane5 = tid & 31;
    const int lane  = tid & 63;          // float4 slot within a row
    const int grp   = tid >> 6;          // 0..3 (row group, 2 rows each)

    __shared__ int wsumM[8];   // per-warp masked sums (prefix before chunk)
    __shared__ int wsumT[8];   // per-warp total sums

    // ---- All loads front-batched. dur pair heads the dependent chain;
    //      chunk-local durations (broadcast int4 x2) and x rows are
    //      independent and fill the latency shadow. ----
    const int* durb = duration + b * SEQ;
    int2 d = ((const int2*)durb)[tid];                    // pair (2t, 2t+1)
    int4 c0 = ((const int4*)(durb + chunk * CHUNK))[0];   // chunk durs 0..3
    int4 c1 = ((const int4*)(durb + chunk * CHUNK))[1];   // chunk durs 4..7

    const float4* __restrict__ xb = (const float4*)x + (b * SEQ) * H4;
    const int r0 = chunk * CHUNK + grp * 2;               // rows r0, r0+1
    float4 v0    = __ldg(&xb[(r0 + 0) * H4 + lane]);
    float4 v1    = __ldg(&xb[(r0 + 1) * H4 + lane]);
    float4 vlast = __ldg(&xb[(SEQ - 1) * H4 + lane]);

    // ---- Two parallel butterfly reductions over the 256 pair-sums:
    //      masked (tid < chunk*4  => durations before this chunk) and total. ----
    int sc = d.x + d.y;
    int sm = (tid < chunk * 4) ? sc : 0;
    #pragma unroll
    for (int off = 16; off >= 1; off >>= 1) {
        sm += __shfl_xor_sync(0xffffffffu, sm, off);
        sc += __shfl_xor_sync(0xffffffffu, sc, off);
    }
    if (lane5 == 0) { wsumM[wid] = sm; wsumT[wid] = sc; }
    __syncthreads();                                      // the ONLY barrier

    int base = 0, total = 0;
    #pragma unroll
    for (int w = 0; w < 8; w++) { base += wsumM[w]; total += wsumT[w]; }

    // ---- Per-group bounds from the chunk-local durations (registers only).
    //      csum[chunk*8 + j] = base + prefix(c[0..j]). ----
    int cd[8] = {c0.x, c0.y, c0.z, c0.w, c1.x, c1.y, c1.z, c1.w};
    int pre = base;
    #pragma unroll
    for (int j = 0; j < 8; j++) {
        if (j < grp * 2) pre += cd[j];
    }
    int lo0 = pre;
    int hi0 = min(pre + cd[grp * 2], TMEL);
    int hi1 = min(pre + cd[grp * 2] + cd[grp * 2 + 1], TMEL);
    lo0 = min(lo0, TMEL);

    // ---- Input-driven expansion: dynamic store loops (fastest measured). ----
    float4* __restrict__ ob = (float4*)out + (b * TMEL) * H4;
    for (int t = lo0; t < hi0; t++)
        ob[t * H4 + lane] = v0;
    for (int t = hi0; t < hi1; t++)
        ob[t * H4 + lane] = v1;

    // ---- Tail: [total, TMEL) replicates row SEQ-1; spread across the 256
    //      (chunk,grp) slots of this batch, stride 256. ----
    int tc = min(total, TMEL);
    for (int t = tc + chunk * 4 + grp; t < TMEL; t += 4 * NCHUNK)
        ob[t * H4 + lane] = vlast;

    // ---- mel_len appended after main output (if buffer includes it). ----
    if (chunk == 0 && tid == 0) {
        const int main_elems = BATCH * TMEL * HID;
        if (out_size >= main_elems + BATCH)
            out[main_elems + b] = (float)tc;
    }
}

extern "C" void kernel_launch(void* const* d_in, const int* in_sizes, int n_in,
                              void* d_out, int out_size) {
    const float* x        = (const float*)d_in[0];
    const int*   duration = (const int*)d_in[1];
    float*       out      = (float*)d_out;

    dim3 grid(NCHUNK, BATCH);   // (64, 32) = 2048 CTAs
    length_regulator_kernel<<<grid, 256>>>(x, duration, out, out_size);
}

// round 14
// speedup vs baseline: 1.1123x; 1.0173x over previous
#include <cuda_runtime.h>

#define BATCH 32
#define SEQ   512
#define HID   256
#define TMEL  2000
#define H4    (HID / 4)      // 64 float4 per row
#define CHUNK 8              // input rows per CTA
#define NCHUNK (SEQ / CHUNK) // 64 CTAs per batch

__global__ __launch_bounds__(256, 8)
void length_regulator_kernel(const float* __restrict__ x,
                             const int* __restrict__ duration,
                             float* __restrict__ out,
                             int out_size) {
    const int b     = blockIdx.y;
    const int chunk = blockIdx.x;        // 0..63
    const int tid   = threadIdx.x;
    const int wid   = tid >> 5;
    const int lane5 = tid & 31;
    const int lane  = tid & 63;          // float4 slot within a row
    const int grp   = tid >> 6;          // 0..3 (row group, 2 rows each)

    __shared__ int csum[SEQ];
    __shared__ int wsum[8];

    // ---- Front-batched loads. x rows are single-use -> streaming (.cs)
    //      so they don't displace the store stream's L2 lines. ----
    const float4* __restrict__ xb = (const float4*)x + (b * SEQ) * H4;
    const int r0 = chunk * CHUNK + grp * 2;       // rows r0, r0+1
    float4 v0 = __ldcs(&xb[(r0 + 0) * H4 + lane]);
    float4 v1 = __ldcs(&xb[(r0 + 1) * H4 + lane]);

    // ---- Inclusive scan of all 512 durations (shuffle-based, 2 barriers). ----
    const int2* dur2 = (const int2*)(duration + b * SEQ);
    int2 d = dur2[tid];
    int sc = d.x + d.y;
    #pragma unroll
    for (int off = 1; off < 32; off <<= 1) {
        int t = __shfl_up_sync(0xffffffffu, sc, off);
        if (lane5 >= off) sc += t;
    }
    if (lane5 == 31) wsum[wid] = sc;
    __syncthreads();
    int wprefix = 0;
    #pragma unroll
    for (int w = 0; w < 8; w++)
        wprefix += (w < wid) ? wsum[w] : 0;
    int inc_hi = sc + wprefix;                    // cumsum at elem 2*tid+1
    csum[2 * tid]     = inc_hi - d.y;
    csum[2 * tid + 1] = inc_hi;
    __syncthreads();

    // ---- Input-driven expansion: row i covers output rows
    //      [csum[i-1], csum[i]); dynamic loops (fastest measured form).
    //      Stores are write-once -> streaming (.cs): evict-first lines,
    //      cheaper L2 dirty-management on the binding store path. ----
    float4* __restrict__ ob = (float4*)out + (b * TMEL) * H4;
    {
        int lo0 = (r0 == 0) ? 0 : csum[r0 - 1];
        int hi0 = min(csum[r0], TMEL);
        int hi1 = min(csum[r0 + 1], TMEL);
        for (int t = lo0; t < hi0; t++)
            __stcs(&ob[t * H4 + lane], v0);
        for (int t = hi0; t < hi1; t++)
            __stcs(&ob[t * H4 + lane], v1);
    }

    // ---- Tail: positions [total, TMEL) replicate row SEQ-1. Spread across
    //      the 256 (chunk,grp) slots of this batch, stride 256. ----
    int total = csum[SEQ - 1];
    int tc = min(total, TMEL);
    int tstart = tc + chunk * 4 + grp;
    if (tstart < TMEL) {
        float4 vlast = __ldg(&xb[(SEQ - 1) * H4 + lane]);  // shared row: keep cached
        for (int t = tstart; t < TMEL; t += 4 * NCHUNK)
            __stcs(&ob[t * H4 + lane], vlast);
    }

    // ---- mel_len appended after main output (if buffer includes it). ----
    if (chunk == 0 && tid == 0) {
        const int main_elems = BATCH * TMEL * HID;
        if (out_size >= main_elems + BATCH)
            out[main_elems + b] = (float)tc;
    }
}

extern "C" void kernel_launch(void* const* d_in, const int* in_sizes, int n_in,
                              void* d_out, int out_size) {
    const float* x        = (const float*)d_in[0];
    const int*   duration = (const int*)d_in[1];
    float*       out      = (float*)d_out;

    dim3 grid(NCHUNK, BATCH);   // (64, 32) = 2048 CTAs
    length_regulator_kernel<<<grid, 256>>>(x, duration, out, out_size);
}